// round 4
// baseline (speedup 1.0000x reference)
#include <cuda_runtime.h>

// Problem shape constants (fixed by the reference setup_inputs)
#define BB   4
#define NC   1024
#define NF   8192
#define NG   8192

// Packed point clouds: {x, y, z, x^2+y^2+z^2}
__device__ float4 g_coarse[BB * NC];
__device__ float4 g_fine  [BB * NF];
__device__ float4 g_gt    [BB * NG];

// Per-block partial sums of per-point min distances.
// Task block ranges: [0,16) coarse->gt, [16,144) gt->coarse,
//                    [144,272) fine->gt, [272,400) gt->fine
__device__ float g_partial[512];

// ---------------------------------------------------------------------------
// Kernel 1: pack all three clouds into float4 (coords + squared norm)
// total points = 4096 + 32768 + 32768 = 69632 = 272 * 256
// ---------------------------------------------------------------------------
__global__ void pack_kernel(const float* __restrict__ c,
                            const float* __restrict__ f,
                            const float* __restrict__ g) {
    int i = blockIdx.x * blockDim.x + threadIdx.x;
    const float* src;
    float4* dst;
    int idx;
    if (i < BB * NC) {
        src = c; dst = g_coarse; idx = i;
    } else if (i < BB * NC + BB * NF) {
        src = f; dst = g_fine; idx = i - BB * NC;
    } else if (i < BB * NC + BB * NF + BB * NG) {
        src = g; dst = g_gt; idx = i - BB * NC - BB * NF;
    } else {
        return;
    }
    float x = src[3 * idx + 0];
    float y = src[3 * idx + 1];
    float z = src[3 * idx + 2];
    dst[idx] = make_float4(x, y, z, fmaf(x, x, fmaf(y, y, z * z)));
}

// ---------------------------------------------------------------------------
// Kernel 2: fused directed chamfer min for all 4 tasks.
// Each thread owns one X point; loops over Y in 256-point smem tiles.
// min_y ||x-y||^2 = x2 + min_y (y2 - 2 x . y)   -> 3 FFMA + 1 FMIN per pair
// ---------------------------------------------------------------------------
__global__ __launch_bounds__(256) void chamfer_min_kernel() {
    __shared__ float4 sY[256];
    __shared__ float wsum[8];

    const int b = blockIdx.x;
    const float4* X;
    const float4* Ybase;
    int NX, NY, bit;
    if (b < 16)       { X = g_coarse; Ybase = g_gt;     NX = NC; NY = NG; bit = b;       }
    else if (b < 144) { X = g_gt;     Ybase = g_coarse; NX = NG; NY = NC; bit = b - 16;  }
    else if (b < 272) { X = g_fine;   Ybase = g_gt;     NX = NF; NY = NG; bit = b - 144; }
    else              { X = g_gt;     Ybase = g_fine;   NX = NG; NY = NF; bit = b - 272; }

    const int tid   = threadIdx.x;
    const int gx    = bit * 256 + tid;      // NX is a multiple of 256 -> in-bounds
    const int batch = gx / NX;
    const int xi    = gx - batch * NX;

    const float4 p = X[batch * NX + xi];
    const float xn0 = -2.0f * p.x;
    const float xn1 = -2.0f * p.y;
    const float xn2 = -2.0f * p.z;
    const float x2  = p.w;

    const float4* Y = Ybase + batch * NY;

    float m0 = 3.4e38f, m1 = 3.4e38f, m2 = 3.4e38f, m3 = 3.4e38f;

    for (int t = 0; t < NY; t += 256) {
        __syncthreads();
        sY[tid] = Y[t + tid];
        __syncthreads();

        #pragma unroll 16
        for (int j = 0; j < 256; j += 4) {
            float4 q0 = sY[j + 0];
            float4 q1 = sY[j + 1];
            float4 q2 = sY[j + 2];
            float4 q3 = sY[j + 3];
            float t0 = fmaf(xn2, q0.z, fmaf(xn1, q0.y, fmaf(xn0, q0.x, q0.w)));
            float t1 = fmaf(xn2, q1.z, fmaf(xn1, q1.y, fmaf(xn0, q1.x, q1.w)));
            float t2 = fmaf(xn2, q2.z, fmaf(xn1, q2.y, fmaf(xn0, q2.x, q2.w)));
            float t3 = fmaf(xn2, q3.z, fmaf(xn1, q3.y, fmaf(xn0, q3.x, q3.w)));
            m0 = fminf(m0, t0);
            m1 = fminf(m1, t1);
            m2 = fminf(m2, t2);
            m3 = fminf(m3, t3);
        }
    }

    float m = fminf(fminf(m0, m1), fminf(m2, m3)) + x2;

    // Deterministic block sum (fixed shuffle tree + fixed serial 8-way)
    float v = m;
    #pragma unroll
    for (int o = 16; o > 0; o >>= 1)
        v += __shfl_down_sync(0xffffffffu, v, o);
    const int lane = tid & 31;
    const int wid  = tid >> 5;
    if (lane == 0) wsum[wid] = v;
    __syncthreads();
    if (tid == 0) {
        float s = 0.0f;
        #pragma unroll
        for (int i = 0; i < 8; i++) s += wsum[i];
        g_partial[blockIdx.x] = s;
    }
}

// ---------------------------------------------------------------------------
// Kernel 3: deterministic reduction of partials + final combine
// ---------------------------------------------------------------------------
__global__ void finalize_kernel(const int* __restrict__ p_coarse,
                                const int* __restrict__ p_fine,
                                float* __restrict__ out) {
    __shared__ float sums[4];
    const int w    = threadIdx.x >> 5;
    const int lane = threadIdx.x & 31;
    const int start[4] = {0, 16, 144, 272};
    const int cnt[4]   = {16, 128, 128, 128};

    if (w < 4) {
        float s = 0.0f;
        for (int i = lane; i < cnt[w]; i += 32)
            s += g_partial[start[w] + i];
        #pragma unroll
        for (int o = 16; o > 0; o >>= 1)
            s += __shfl_down_sync(0xffffffffu, s, o);
        if (lane == 0) sums[w] = s;
    }
    __syncthreads();
    if (threadIdx.x == 0) {
        const float inv_c  = 1.0f / (float)(BB * NC);  // 1/4096
        const float inv_g  = 1.0f / (float)(BB * NG);  // 1/32768
        const float inv_f  = 1.0f / (float)(BB * NF);  // 1/32768
        float loss_coarse = (sums[0] * inv_c + sums[1] * inv_g) * (float)p_coarse[0];
        float loss_fine   = (sums[2] * inv_f + sums[3] * inv_g) * (float)p_fine[0];
        out[0] = loss_coarse;
        out[1] = loss_fine;
    }
}

// ---------------------------------------------------------------------------
// Launch
// ---------------------------------------------------------------------------
extern "C" void kernel_launch(void* const* d_in, const int* in_sizes, int n_in,
                              void* d_out, int out_size) {
    const float* coarse = (const float*)d_in[0];   // [4,1024,3]
    const float* fine   = (const float*)d_in[1];   // [4,8192,3]
    const float* gt     = (const float*)d_in[2];   // [4,8192,3]
    const int*   pc     = (const int*)d_in[3];     // param_coarse
    const int*   pf     = (const int*)d_in[4];     // param_fine
    float* out = (float*)d_out;

    pack_kernel<<<272, 256>>>(coarse, fine, gt);
    chamfer_min_kernel<<<400, 256>>>();
    finalize_kernel<<<1, 128>>>(pc, pf, out);
}

// round 5
// speedup vs baseline: 1.0028x; 1.0028x over previous
#include <cuda_runtime.h>

// Problem shape constants (fixed by the reference setup_inputs)
#define BB   4
#define NC   1024
#define NF   8192
#define NG   8192

// Packed point clouds: {x, y, z, x^2+y^2+z^2}
__device__ float4 g_coarse[BB * NC];
__device__ float4 g_fine  [BB * NF];
__device__ float4 g_gt    [BB * NG];

// Per-block partial sums of per-point min distances.
// Task block ranges: [0,16) coarse->gt, [16,144) gt->coarse,
//                    [144,272) fine->gt, [272,400) gt->fine
__device__ float g_partial[512];

// ---------------------------------------------------------------------------
// Kernel 1: pack all three clouds into float4 (coords + squared norm)
// total points = 4096 + 32768 + 32768 = 69632 = 272 * 256
// ---------------------------------------------------------------------------
__global__ void pack_kernel(const float* __restrict__ c,
                            const float* __restrict__ f,
                            const float* __restrict__ g) {
    int i = blockIdx.x * blockDim.x + threadIdx.x;
    const float* src;
    float4* dst;
    int idx;
    if (i < BB * NC) {
        src = c; dst = g_coarse; idx = i;
    } else if (i < BB * NC + BB * NF) {
        src = f; dst = g_fine; idx = i - BB * NC;
    } else if (i < BB * NC + BB * NF + BB * NG) {
        src = g; dst = g_gt; idx = i - BB * NC - BB * NF;
    } else {
        return;
    }
    float x = src[3 * idx + 0];
    float y = src[3 * idx + 1];
    float z = src[3 * idx + 2];
    dst[idx] = make_float4(x, y, z, fmaf(x, x, fmaf(y, y, z * z)));
}

// ---------------------------------------------------------------------------
// Kernel 2: fused directed chamfer min for all 4 tasks.
// Each thread owns one X point; loops over Y in 256-point smem tiles.
// min_y ||x-y||^2 = x2 + min_y (y2 - 2 x . y)   -> 3 FFMA + 1 FMIN per pair
// ---------------------------------------------------------------------------
__global__ __launch_bounds__(256) void chamfer_min_kernel() {
    __shared__ float4 sY[256];
    __shared__ float wsum[8];

    const int b = blockIdx.x;
    const float4* X;
    const float4* Ybase;
    int NX, NY, bit;
    if (b < 16)       { X = g_coarse; Ybase = g_gt;     NX = NC; NY = NG; bit = b;       }
    else if (b < 144) { X = g_gt;     Ybase = g_coarse; NX = NG; NY = NC; bit = b - 16;  }
    else if (b < 272) { X = g_fine;   Ybase = g_gt;     NX = NF; NY = NG; bit = b - 144; }
    else              { X = g_gt;     Ybase = g_fine;   NX = NG; NY = NF; bit = b - 272; }

    const int tid   = threadIdx.x;
    const int gx    = bit * 256 + tid;      // NX is a multiple of 256 -> in-bounds
    const int batch = gx / NX;
    const int xi    = gx - batch * NX;

    const float4 p = X[batch * NX + xi];
    const float xn0 = -2.0f * p.x;
    const float xn1 = -2.0f * p.y;
    const float xn2 = -2.0f * p.z;
    const float x2  = p.w;

    const float4* Y = Ybase + batch * NY;

    float m0 = 3.4e38f, m1 = 3.4e38f, m2 = 3.4e38f, m3 = 3.4e38f;

    for (int t = 0; t < NY; t += 256) {
        __syncthreads();
        sY[tid] = Y[t + tid];
        __syncthreads();

        #pragma unroll 16
        for (int j = 0; j < 256; j += 4) {
            float4 q0 = sY[j + 0];
            float4 q1 = sY[j + 1];
            float4 q2 = sY[j + 2];
            float4 q3 = sY[j + 3];
            float t0 = fmaf(xn2, q0.z, fmaf(xn1, q0.y, fmaf(xn0, q0.x, q0.w)));
            float t1 = fmaf(xn2, q1.z, fmaf(xn1, q1.y, fmaf(xn0, q1.x, q1.w)));
            float t2 = fmaf(xn2, q2.z, fmaf(xn1, q2.y, fmaf(xn0, q2.x, q2.w)));
            float t3 = fmaf(xn2, q3.z, fmaf(xn1, q3.y, fmaf(xn0, q3.x, q3.w)));
            m0 = fminf(m0, t0);
            m1 = fminf(m1, t1);
            m2 = fminf(m2, t2);
            m3 = fminf(m3, t3);
        }
    }

    float m = fminf(fminf(m0, m1), fminf(m2, m3)) + x2;

    // Deterministic block sum (fixed shuffle tree + fixed serial 8-way)
    float v = m;
    #pragma unroll
    for (int o = 16; o > 0; o >>= 1)
        v += __shfl_down_sync(0xffffffffu, v, o);
    const int lane = tid & 31;
    const int wid  = tid >> 5;
    if (lane == 0) wsum[wid] = v;
    __syncthreads();
    if (tid == 0) {
        float s = 0.0f;
        #pragma unroll
        for (int i = 0; i < 8; i++) s += wsum[i];
        g_partial[blockIdx.x] = s;
    }
}

// ---------------------------------------------------------------------------
// Kernel 3: deterministic reduction of partials + final combine
// ---------------------------------------------------------------------------
__global__ void finalize_kernel(const int* __restrict__ p_coarse,
                                const int* __restrict__ p_fine,
                                float* __restrict__ out) {
    __shared__ float sums[4];
    const int w    = threadIdx.x >> 5;
    const int lane = threadIdx.x & 31;
    const int start[4] = {0, 16, 144, 272};
    const int cnt[4]   = {16, 128, 128, 128};

    if (w < 4) {
        float s = 0.0f;
        for (int i = lane; i < cnt[w]; i += 32)
            s += g_partial[start[w] + i];
        #pragma unroll
        for (int o = 16; o > 0; o >>= 1)
            s += __shfl_down_sync(0xffffffffu, s, o);
        if (lane == 0) sums[w] = s;
    }
    __syncthreads();
    if (threadIdx.x == 0) {
        const float inv_c  = 1.0f / (float)(BB * NC);  // 1/4096
        const float inv_g  = 1.0f / (float)(BB * NG);  // 1/32768
        const float inv_f  = 1.0f / (float)(BB * NF);  // 1/32768
        float loss_coarse = (sums[0] * inv_c + sums[1] * inv_g) * (float)p_coarse[0];
        float loss_fine   = (sums[2] * inv_f + sums[3] * inv_g) * (float)p_fine[0];
        out[0] = loss_coarse;
        out[1] = loss_fine;
    }
}

// ---------------------------------------------------------------------------
// Launch
// ---------------------------------------------------------------------------
extern "C" void kernel_launch(void* const* d_in, const int* in_sizes, int n_in,
                              void* d_out, int out_size) {
    const float* coarse = (const float*)d_in[0];   // [4,1024,3]
    const float* fine   = (const float*)d_in[1];   // [4,8192,3]
    const float* gt     = (const float*)d_in[2];   // [4,8192,3]
    const int*   pc     = (const int*)d_in[3];     // param_coarse
    const int*   pf     = (const int*)d_in[4];     // param_fine
    float* out = (float*)d_out;

    pack_kernel<<<272, 256>>>(coarse, fine, gt);
    chamfer_min_kernel<<<400, 256>>>();
    finalize_kernel<<<1, 128>>>(pc, pf, out);
}